// round 6
// baseline (speedup 1.0000x reference)
#include <cuda_runtime.h>

#define RSQRT2 0.70710678118654752440f

typedef unsigned long long u64;

__device__ __forceinline__ u64 pk2(float lo, float hi) {
    u64 r;
    asm("mov.b64 %0, {%1, %2};" : "=l"(r) : "f"(lo), "f"(hi));
    return r;
}
__device__ __forceinline__ void unpk2(u64 v, float& lo, float& hi) {
    asm("mov.b64 {%0, %1}, %2;" : "=f"(lo), "=f"(hi) : "l"(v));
}
__device__ __forceinline__ u64 bc2(float a) { return pk2(a, a); }
__device__ __forceinline__ u64 fma2(u64 a, u64 b, u64 c) {
    u64 d;
    asm("fma.rn.f32x2 %0, %1, %2, %3;" : "=l"(d) : "l"(a), "l"(b), "l"(c));
    return d;
}
__device__ __forceinline__ u64 mul2(u64 a, u64 b) {
    u64 d;
    asm("mul.rn.f32x2 %0, %1, %2;" : "=l"(d) : "l"(a), "l"(b));
    return d;
}
__device__ __forceinline__ u64 add2(u64 a, u64 b) {
    u64 d;
    asm("add.rn.f32x2 %0, %1, %2;" : "=l"(d) : "l"(a), "l"(b));
    return d;
}
#define SGN2 0x8000000080000000ULL
__device__ __forceinline__ u64 neg2(u64 a) { return a ^ SGN2; }  // ALU pipe
__device__ __forceinline__ u64 sub2(u64 a, u64 b) { return add2(a, neg2(b)); }

// In-place left-multiply of column (p,q) by Rz / Ry; g=(cos(a/2),sin(a/2)).
__device__ __forceinline__ void rz_pq(float2& p, float2& q, float gc, float gs) {
    p = make_float2(gc * p.x + gs * p.y, gc * p.y - gs * p.x);
    q = make_float2(gc * q.x + gs * q.y, gc * q.y - gs * q.x);
}
__device__ __forceinline__ void ry_pq(float2& p, float2& q, float gc, float gs) {
    float px = gc * p.x - gs * q.x;
    float py = gc * p.y + gs * q.y;
    float qx = gc * q.x + gs * p.x;
    float qy = gc * q.y - gs * p.y;
    p = make_float2(px, py);
    q = make_float2(qx, qy);
}

// Packed apply of U=[[p,q],[q*,-p*]] on packed-index pair (k0,k1=k0+S).
__device__ __forceinline__ void pair_pq(u64* SX, u64* SY, int k0, int k1,
                                        u64 PX, u64 PY, u64 QX, u64 QY,
                                        u64 PXn, u64 PYn, u64 QYn) {
    u64 X0 = SX[k0], Y0 = SY[k0], X1 = SX[k1], Y1 = SY[k1];
    u64 nX0 = fma2(PX, X0, fma2(PYn, Y0, fma2(QX, X1, mul2(QYn, Y1))));
    u64 nY0 = fma2(PX, Y0, fma2(PY, X0, fma2(QX, Y1, mul2(QY, X1))));
    u64 nX1 = fma2(QX, X0, fma2(QY, Y0, fma2(PXn, X1, mul2(PYn, Y1))));
    u64 nY1 = fma2(QX, Y0, fma2(QYn, X0, fma2(PXn, Y1, mul2(PY, X1))));
    SX[k0] = nX0; SY[k0] = nY0; SX[k1] = nX1; SY[k1] = nY1;
}

// Load 16 window pixel values (compacted order, zero-filled) for window (wi,wj).
__device__ __forceinline__ void loadwin(const float* __restrict__ xi, int wi,
                                        int wj, float* v) {
    const float* b = xi + wi * 56 + wj * 2;
    bool fh = wi < 13, fw = wj < 13;
    if (fh && fw) {
        v[0] = b[0];  v[1] = b[1];  v[2] = b[2];  v[3] = b[3];
        v[4] = b[28]; v[5] = b[29]; v[6] = b[30]; v[7] = b[31];
        v[8] = b[56]; v[9] = b[57]; v[10] = b[58]; v[11] = b[59];
        v[12] = b[84]; v[13] = b[85]; v[14] = b[86]; v[15] = b[87];
    } else if (fh) {  // h=4, w=2: slot k -> (k/2, k%2)
        v[0] = b[0];  v[1] = b[1];  v[2] = b[28]; v[3] = b[29];
        v[4] = b[56]; v[5] = b[57]; v[6] = b[84]; v[7] = b[85];
        v[8] = 0.f; v[9] = 0.f; v[10] = 0.f; v[11] = 0.f;
        v[12] = 0.f; v[13] = 0.f; v[14] = 0.f; v[15] = 0.f;
    } else if (fw) {  // h=2, w=4: slot k -> (k/4, k%4)
        v[0] = b[0];  v[1] = b[1];  v[2] = b[2];  v[3] = b[3];
        v[4] = b[28]; v[5] = b[29]; v[6] = b[30]; v[7] = b[31];
        v[8] = 0.f; v[9] = 0.f; v[10] = 0.f; v[11] = 0.f;
        v[12] = 0.f; v[13] = 0.f; v[14] = 0.f; v[15] = 0.f;
    } else {  // 2x2
        v[0] = b[0]; v[1] = b[1]; v[2] = b[28]; v[3] = b[29];
        v[4] = 0.f; v[5] = 0.f; v[6] = 0.f; v[7] = 0.f;
        v[8] = 0.f; v[9] = 0.f; v[10] = 0.f; v[11] = 0.f;
        v[12] = 0.f; v[13] = 0.f; v[14] = 0.f; v[15] = 0.f;
    }
}

__global__ __launch_bounds__(32) void multi_encoding_kernel(
    const float* __restrict__ x, const float* __restrict__ crz_t,
    const float* __restrict__ ry_t, const float* __restrict__ fc1w,
    const float* __restrict__ fc1b, const float* __restrict__ fc2w,
    const float* __restrict__ fc2b, float* __restrict__ out, int B) {
    int img = blockIdx.x * 32 + threadIdx.x;
    if (img >= B) return;
    const float* xi = x + (size_t)img * 784;

    // ---- loop-invariant constants ----
    float th = __ldg(crz_t);
    float cs1, sn1;
    sincosf(0.5f * th, &sn1, &cs1);
    float c2 = cs1 * cs1 - sn1 * sn1, s2 = 2.f * cs1 * sn1;  // theta
    float c4 = c2 * c2 - s2 * s2, s4 = 2.f * c2 * s2;         // 2*theta

    // CRZ diagonal phases per amplitude n (sign table 0,-1,-1,0,-1,-2,0,1,
    // -1,0,-2,1,0,1,1,4), packed as lanes (2k, 2k+1).
    u64 PHX[8], PHY[8];
    PHX[0] = pk2(1.f, cs1);   PHY[0] = pk2(0.f, -sn1);   // n=0,1
    PHX[1] = pk2(cs1, 1.f);   PHY[1] = pk2(-sn1, 0.f);   // n=2,3
    PHX[2] = pk2(cs1, c2);    PHY[2] = pk2(-sn1, -s2);   // n=4,5
    PHX[3] = pk2(1.f, cs1);   PHY[3] = pk2(0.f, sn1);    // n=6,7
    PHX[4] = pk2(cs1, 1.f);   PHY[4] = pk2(-sn1, 0.f);   // n=8,9
    PHX[5] = pk2(c2, cs1);    PHY[5] = pk2(-s2, sn1);    // n=10,11
    PHX[6] = pk2(1.f, cs1);   PHY[6] = pk2(0.f, sn1);    // n=12,13
    PHX[7] = pk2(cs1, c4);    PHY[7] = pk2(sn1, s4);     // n=14,15

    float tr = __ldg(ry_t);
    float cr, sr;
    sincosf(0.5f * tr, &sr, &cr);
    float a1 = (cr + sr) * RSQRT2;  // base H*Ry for steps >= 1
    float b1 = (cr - sr) * RSQRT2;
    float mc = cr * cr - sr * sr;   // cos(tr)
    float ms2 = 4.f * cr * sr;      // 2*sin(tr)
    float ms2h = 0.5f * ms2;

    // ---- state |0000>, packed SoA: SX[k]=(x_{2k},x_{2k+1}) ----
    u64 SX[8], SY[8];
#pragma unroll
    for (int k = 0; k < 8; k++) { SX[k] = 0ULL; SY[k] = 0ULL; }
    SX[0] = pk2(1.f, 0.f);

    float acc[20];
#pragma unroll
    for (int j = 0; j < 20; j++) acc[j] = 0.f;

    float Ab = RSQRT2, Bb = RSQRT2;  // step-0 base is plain H
    const float4* w4 = reinterpret_cast<const float4*>(fc1w);

    float vc[16];
    loadwin(xi, 0, 0, vc);
    int wi = 0, wj = 0;

#pragma unroll 1
    for (int widx = 0; widx < 196; widx++) {
        // ---- prefetch next window's pixels (hides DRAM latency) ----
        float vn[16];
        int nwi = wi, nwj = wj + 1;
        if (nwj == 14) { nwj = 0; nwi++; }
        if (widx < 195) loadwin(xi, nwi, nwj, vn);

        // ---- sincos of half-pixels (missing slots are 0 -> (1,0)) ----
        float gc[16], gs[16];
#pragma unroll
        for (int k = 0; k < 16; k++) {
            __sincosf(0.5f * vc[k], &gs[k], &gc[k]);
        }

        // ---- build per-wire unitaries (scalar) ----
        float2 p0 = make_float2(Ab, 0.f), q0 = make_float2(Bb, 0.f);
        rz_pq(p0, q0, gc[0], gs[0]); ry_pq(p0, q0, gc[1], gs[1]);
        rz_pq(p0, q0, gc[2], gs[2]); ry_pq(p0, q0, gc[3], gs[3]);
        rz_pq(p0, q0, gc[4], gs[4]);
        float2 p1 = make_float2(Ab, 0.f), q1 = make_float2(Bb, 0.f);
        rz_pq(p1, q1, gc[5], gs[5]); ry_pq(p1, q1, gc[6], gs[6]);
        rz_pq(p1, q1, gc[7], gs[7]); ry_pq(p1, q1, gc[8], gs[8]);
        rz_pq(p1, q1, gc[9], gs[9]);
        float2 p2 = make_float2(Ab, 0.f), q2 = make_float2(Bb, 0.f);
        rz_pq(p2, q2, gc[10], gs[10]); ry_pq(p2, q2, gc[11], gs[11]);
        rz_pq(p2, q2, gc[12], gs[12]); ry_pq(p2, q2, gc[13], gs[13]);
        rz_pq(p2, q2, gc[14], gs[14]);
        float2 p3 = make_float2(Ab * gc[15], -Ab * gs[15]);
        float2 q3 = make_float2(Bb * gc[15], -Bb * gs[15]);

        // ---- wire 0 (packed stride 4) ----
        {
            u64 PX = bc2(p0.x), PY = bc2(p0.y), QX = bc2(q0.x), QY = bc2(q0.y);
            u64 PXn = neg2(PX), PYn = neg2(PY), QYn = neg2(QY);
            pair_pq(SX, SY, 0, 4, PX, PY, QX, QY, PXn, PYn, QYn);
            pair_pq(SX, SY, 1, 5, PX, PY, QX, QY, PXn, PYn, QYn);
            pair_pq(SX, SY, 2, 6, PX, PY, QX, QY, PXn, PYn, QYn);
            pair_pq(SX, SY, 3, 7, PX, PY, QX, QY, PXn, PYn, QYn);
        }
        // ---- wire 1 (packed stride 2) ----
        {
            u64 PX = bc2(p1.x), PY = bc2(p1.y), QX = bc2(q1.x), QY = bc2(q1.y);
            u64 PXn = neg2(PX), PYn = neg2(PY), QYn = neg2(QY);
            pair_pq(SX, SY, 0, 2, PX, PY, QX, QY, PXn, PYn, QYn);
            pair_pq(SX, SY, 1, 3, PX, PY, QX, QY, PXn, PYn, QYn);
            pair_pq(SX, SY, 4, 6, PX, PY, QX, QY, PXn, PYn, QYn);
            pair_pq(SX, SY, 5, 7, PX, PY, QX, QY, PXn, PYn, QYn);
        }
        // ---- wire 2 (packed stride 1) ----
        {
            u64 PX = bc2(p2.x), PY = bc2(p2.y), QX = bc2(q2.x), QY = bc2(q2.y);
            u64 PXn = neg2(PX), PYn = neg2(PY), QYn = neg2(QY);
            pair_pq(SX, SY, 0, 1, PX, PY, QX, QY, PXn, PYn, QYn);
            pair_pq(SX, SY, 2, 3, PX, PY, QX, QY, PXn, PYn, QYn);
            pair_pq(SX, SY, 4, 5, PX, PY, QX, QY, PXn, PYn, QYn);
            pair_pq(SX, SY, 6, 7, PX, PY, QX, QY, PXn, PYn, QYn);
        }
        // ---- wire 3 (intra-register; coefficient-vector form) ----
        {
            u64 A1 = pk2(p3.x, q3.x);
            u64 A2 = pk2(-p3.y, q3.y);
            u64 A3 = pk2(q3.x, -p3.x);
            u64 A4 = pk2(-q3.y, -p3.y);
            u64 B2 = pk2(p3.y, -q3.y);
            u64 B4 = pk2(q3.y, p3.y);
#pragma unroll
            for (int k = 0; k < 8; k++) {
                float x0, x1, y0, y1;
                unpk2(SX[k], x0, x1);
                unpk2(SY[k], y0, y1);
                u64 bx0 = bc2(x0), bx1 = bc2(x1), by0 = bc2(y0), by1 = bc2(y1);
                SX[k] = fma2(bx0, A1, fma2(by0, A2, fma2(bx1, A3, mul2(by1, A4))));
                SY[k] = fma2(by0, A1, fma2(bx0, B2, fma2(by1, A3, mul2(bx1, B4))));
            }
        }
        // ---- CRZ diagonal (packed, per-lane phases) ----
#pragma unroll
        for (int k = 0; k < 8; k++) {
            u64 X = SX[k], Y = SY[k];
            SX[k] = fma2(PHX[k], X, neg2(mul2(PHY[k], Y)));
            SY[k] = fma2(PHX[k], Y, mul2(PHY[k], X));
        }

        // ---- measurement with rotated operator ----
        u64 prv[8];
#pragma unroll
        for (int k = 0; k < 8; k++)
            prv[k] = fma2(SY[k], SY[k], mul2(SX[k], SX[k]));
        u64 g01 = add2(prv[0], prv[1]), g23 = add2(prv[2], prv[3]);
        u64 g45 = add2(prv[4], prv[5]), g67 = add2(prv[6], prv[7]);
        u64 s03 = add2(g01, g23), s47 = add2(g45, g67);
        u64 Sall = add2(s03, s47);
        u64 d0p = sub2(s03, s47);
        u64 d1p = add2(sub2(g01, g23), sub2(g45, g67));
        u64 o01 = sub2(prv[0], prv[1]), o23 = sub2(prv[2], prv[3]);
        u64 o45 = sub2(prv[4], prv[5]), o67 = sub2(prv[6], prv[7]);
        u64 d2p = add2(add2(o01, o23), add2(o45, o67));
        float lo, hi, d0, d1, d2, d3;
        unpk2(d0p, lo, hi); d0 = lo + hi;
        unpk2(d1p, lo, hi); d1 = lo + hi;
        unpk2(d2p, lo, hi); d2 = lo + hi;
        unpk2(Sall, lo, hi); d3 = lo - hi;

        // cross terms x_w = sum Re(conj(s_n) s_{n+R})
        u64 xa;
        xa = mul2(SX[0], SX[4]); xa = fma2(SY[0], SY[4], xa);
        xa = fma2(SX[1], SX[5], xa); xa = fma2(SY[1], SY[5], xa);
        xa = fma2(SX[2], SX[6], xa); xa = fma2(SY[2], SY[6], xa);
        xa = fma2(SX[3], SX[7], xa); xa = fma2(SY[3], SY[7], xa);
        unpk2(xa, lo, hi); float x0 = lo + hi;
        xa = mul2(SX[0], SX[2]); xa = fma2(SY[0], SY[2], xa);
        xa = fma2(SX[1], SX[3], xa); xa = fma2(SY[1], SY[3], xa);
        xa = fma2(SX[4], SX[6], xa); xa = fma2(SY[4], SY[6], xa);
        xa = fma2(SX[5], SX[7], xa); xa = fma2(SY[5], SY[7], xa);
        unpk2(xa, lo, hi); float x1 = lo + hi;
        xa = mul2(SX[0], SX[1]); xa = fma2(SY[0], SY[1], xa);
        xa = fma2(SX[2], SX[3], xa); xa = fma2(SY[2], SY[3], xa);
        xa = fma2(SX[4], SX[5], xa); xa = fma2(SY[4], SY[5], xa);
        xa = fma2(SX[6], SX[7], xa); xa = fma2(SY[6], SY[7], xa);
        unpk2(xa, lo, hi); float x2 = lo + hi;
        float x3 = 0.f;
#pragma unroll
        for (int k = 0; k < 8; k++) {
            float ax0, ax1, ay0, ay1;
            unpk2(SX[k], ax0, ax1);
            unpk2(SY[k], ay0, ay1);
            x3 += ax0 * ax1 + ay0 * ay1;
        }

        float f0 = mc * d0 - ms2 * x0;
        float f1 = mc * d1 - ms2 * x1;
        float f2 = mc * d2 - ms2 * x2;
        float f3 = mc * d3 - ms2 * x3;
        (void)ms2h;

        // ---- fc1 accumulation (columns 4*widx..4*widx+3) ----
#pragma unroll
        for (int jj = 0; jj < 20; jj++) {
            float4 wv = __ldg(&w4[jj * 196 + widx]);
            acc[jj] += f0 * wv.x + f1 * wv.y + f2 * wv.z + f3 * wv.w;
        }

        // ---- advance ----
        Ab = a1;
        Bb = b1;
        wi = nwi;
        wj = nwj;
        if (widx < 195) {
#pragma unroll
            for (int k = 0; k < 16; k++) vc[k] = vn[k];
        }
    }

    // ---- fc1 bias + leaky relu + fc2 ----
    float o0 = __ldg(fc2b + 0);
    float o1 = __ldg(fc2b + 1);
#pragma unroll
    for (int jj = 0; jj < 20; jj++) {
        float v = acc[jj] + __ldg(fc1b + jj);
        v = v > 0.f ? v : 0.1f * v;
        o0 += v * __ldg(fc2w + jj);
        o1 += v * __ldg(fc2w + 20 + jj);
    }
    reinterpret_cast<float2*>(out)[img] = make_float2(o0, o1);
}

extern "C" void kernel_launch(void* const* d_in, const int* in_sizes, int n_in,
                              void* d_out, int out_size) {
    const float* x = (const float*)d_in[0];
    const float* crz_t = (const float*)d_in[1];
    const float* ry_t = (const float*)d_in[2];
    const float* fc1w = (const float*)d_in[3];
    const float* fc1b = (const float*)d_in[4];
    const float* fc2w = (const float*)d_in[5];
    const float* fc2b = (const float*)d_in[6];
    float* out = (float*)d_out;

    int B = in_sizes[0] / 784;
    int grid = (B + 31) / 32;
    multi_encoding_kernel<<<grid, 32>>>(x, crz_t, ry_t, fc1w, fc1b, fc2w, fc2b,
                                        out, B);
}

// round 8
// speedup vs baseline: 1.1170x; 1.1170x over previous
#include <cuda_runtime.h>

#define RSQRT2 0.70710678118654752440f

typedef unsigned long long u64;

__device__ __forceinline__ u64 pk2(float lo, float hi) {
    u64 r;
    asm("mov.b64 %0, {%1, %2};" : "=l"(r) : "f"(lo), "f"(hi));
    return r;
}
__device__ __forceinline__ void unpk2(u64 v, float& lo, float& hi) {
    asm("mov.b64 {%0, %1}, %2;" : "=f"(lo), "=f"(hi) : "l"(v));
}
__device__ __forceinline__ u64 bc2(float a) { return pk2(a, a); }
__device__ __forceinline__ u64 fma2(u64 a, u64 b, u64 c) {
    u64 d;
    asm("fma.rn.f32x2 %0, %1, %2, %3;" : "=l"(d) : "l"(a), "l"(b), "l"(c));
    return d;
}
__device__ __forceinline__ u64 mul2(u64 a, u64 b) {
    u64 d;
    asm("mul.rn.f32x2 %0, %1, %2;" : "=l"(d) : "l"(a), "l"(b));
    return d;
}
__device__ __forceinline__ u64 add2(u64 a, u64 b) {
    u64 d;
    asm("add.rn.f32x2 %0, %1, %2;" : "=l"(d) : "l"(a), "l"(b));
    return d;
}
#define SGN2 0x8000000080000000ULL
__device__ __forceinline__ u64 neg2(u64 a) { return a ^ SGN2; }
__device__ __forceinline__ u64 sub2(u64 a, u64 b) { return add2(a, neg2(b)); }

__device__ __forceinline__ u64 shflx64(u64 v, int m) {
    return __shfl_xor_sync(0xffffffffu, v, m);
}

// Left-multiply column (px,py,qx,qy) of U=[[p,q],[q*,-p*]] by Rz / Ry.
#define RZ_G(c, s)                         \
    do {                                   \
        float _px = c * px + s * py;       \
        float _py = c * py - s * px;       \
        float _qx = c * qx + s * qy;       \
        float _qy = c * qy - s * qx;       \
        px = _px; py = _py; qx = _qx; qy = _qy; \
    } while (0)
#define RY_G(c, s)                         \
    do {                                   \
        float _px = c * px - s * qx;       \
        float _py = c * py + s * qy;       \
        float _qx = c * qx + s * px;       \
        float _qy = c * qy - s * py;       \
        px = _px; py = _py; qx = _qx; qy = _qy; \
    } while (0)

__global__ __launch_bounds__(128) void multi_encoding_kernel(
    const float* __restrict__ x, const float* __restrict__ crz_t,
    const float* __restrict__ ry_t, const float* __restrict__ fc1w,
    const float* __restrict__ fc1b, const float* __restrict__ fc2w,
    const float* __restrict__ fc2b, float* __restrict__ out, int B) {
    int tid = threadIdx.x;
    int r = tid & 3;                       // lane within quad = (bit3,bit2) of amps
    int img_raw = blockIdx.x * 32 + (tid >> 2);
    int img = img_raw < B ? img_raw : B - 1;   // clamp (quad-coherent)
    const float* xi = x + (size_t)img * 784;

    // ---- constants ----
    float th = __ldg(crz_t);
    float cs1, sn1;
    sincosf(0.5f * th, &sn1, &cs1);
    float c2 = cs1 * cs1 - sn1 * sn1, s2 = 2.f * cs1 * sn1;
    float c4 = c2 * c2 - s2 * s2, s4 = 2.f * c2 * s2;

    float tr = __ldg(ry_t);
    float cr, sr;
    sincosf(0.5f * tr, &sr, &cr);
    float a1 = (cr + sr) * RSQRT2;   // base H*Ry for steps >= 1
    float b1 = (cr - sr) * RSQRT2;
    float mc = cr * cr - sr * sr;    // cos(tr)
    float ms2 = 4.f * cr * sr;       // 2 sin(tr)
    float ms2h = 2.f * cr * sr;      // sin(tr): cross-wire terms double-counted

    // ---- per-lane CRZ phases for amps 4r..4r+3 ----
    // sign table n=0..15: 0,-1,-1,0, -1,-2,0,1, -1,0,-2,1, 0,1,1,4
    u64 PHX0, PHY0, PHX1, PHY1;
    if (r == 0) {
        PHX0 = pk2(1.f, cs1);  PHY0 = pk2(0.f, -sn1);
        PHX1 = pk2(cs1, 1.f);  PHY1 = pk2(-sn1, 0.f);
    } else if (r == 1) {
        PHX0 = pk2(cs1, c2);   PHY0 = pk2(-sn1, -s2);
        PHX1 = pk2(1.f, cs1);  PHY1 = pk2(0.f, sn1);
    } else if (r == 2) {
        PHX0 = pk2(cs1, 1.f);  PHY0 = pk2(-sn1, 0.f);
        PHX1 = pk2(c2, cs1);   PHY1 = pk2(-s2, sn1);
    } else {
        PHX0 = pk2(1.f, cs1);  PHY0 = pk2(0.f, sn1);
        PHX1 = pk2(cs1, c4);   PHY1 = pk2(sn1, s4);
    }

    bool side0 = (r & 2) != 0;   // bit3 of owned amps
    bool side1 = (r & 1) != 0;   // bit2
    float sgn0 = side0 ? -1.f : 1.f;
    float sgn1 = side1 ? -1.f : 1.f;

    // ---- state: lane owns amps 4r..4r+3; X0=(x_{4r},x_{4r+1}), X1=(x_{4r+2},x_{4r+3})
    u64 X0 = 0ULL, X1 = 0ULL, Y0 = 0ULL, Y1 = 0ULL;
    if (r == 0) X0 = pk2(1.f, 0.f);

    float acc[5];
#pragma unroll
    for (int t = 0; t < 5; t++) acc[t] = 0.f;

    float Ab = RSQRT2, Bb = RSQRT2;   // step-0 base is plain H
    const float4* w4 = reinterpret_cast<const float4*>(fc1w);
    int slot0 = 5 * r;                // this lane's first gate slot (r=3 -> 15)

    int widx = 0;
#pragma unroll 1
    for (int wi = 0; wi < 14; wi++) {
        int hdec = (wi == 13) ? 1 : 0;
#pragma unroll 1
        for (int wj = 0; wj < 14; wj++) {
            bool wlast = (wj == 13);
            int sh = wlast ? 1 : 2;
            int msk = wlast ? 1 : 3;
            int lim = 16 >> (hdec + (wlast ? 1 : 0));
            const float* bp = xi + wi * 56 + wj * 2;

            // ---- this lane's 5 gate angles (slots slot0..slot0+4, 0 if invalid)
            float gc[5], gs[5];
#pragma unroll
            for (int k = 0; k < 5; k++) {
                int slot = slot0 + k;
                int off = (slot >> sh) * 28 + (slot & msk);
                float v = (slot < lim) ? __ldg(bp + off) : 0.f;
                __sincosf(0.5f * v, &gs[k], &gc[k]);
            }

            // ---- build this lane's wire unitary: Rz g4 . Ry g3 . Rz g2 . Ry g1 . Rz g0 . Base
            float px = Ab, py = 0.f, qx = Bb, qy = 0.f;
            RZ_G(gc[0], gs[0]);
            RY_G(gc[1], gs[1]);
            RZ_G(gc[2], gs[2]);
            RY_G(gc[3], gs[3]);
            RZ_G(gc[4], gs[4]);

            // ---- share all four wires' (p,q) within the quad ----
            float p0x = __shfl_sync(0xffffffffu, px, 0, 4);
            float p0y = __shfl_sync(0xffffffffu, py, 0, 4);
            float q0x = __shfl_sync(0xffffffffu, qx, 0, 4);
            float q0y = __shfl_sync(0xffffffffu, qy, 0, 4);
            float p1x = __shfl_sync(0xffffffffu, px, 1, 4);
            float p1y = __shfl_sync(0xffffffffu, py, 1, 4);
            float q1x = __shfl_sync(0xffffffffu, qx, 1, 4);
            float q1y = __shfl_sync(0xffffffffu, qy, 1, 4);
            float p2x = __shfl_sync(0xffffffffu, px, 2, 4);
            float p2y = __shfl_sync(0xffffffffu, py, 2, 4);
            float q2x = __shfl_sync(0xffffffffu, qx, 2, 4);
            float q2y = __shfl_sync(0xffffffffu, qy, 2, 4);
            float p3x = __shfl_sync(0xffffffffu, px, 3, 4);
            float p3y = __shfl_sync(0xffffffffu, py, 3, 4);
            float q3x = __shfl_sync(0xffffffffu, qx, 3, 4);
            float q3y = __shfl_sync(0xffffffffu, qy, 3, 4);

            // ---- wire 0 (bit3, cross-lane xor 2) ----
            {
                u64 Ax = bc2(side0 ? -p0x : p0x);
                u64 Bx = bc2(-p0y);
                u64 Cx = bc2(q0x);
                u64 Dx = bc2(side0 ? q0y : -q0y);
                u64 nBx = neg2(Bx), nDx = neg2(Dx);
                u64 X0p = shflx64(X0, 2), Y0p = shflx64(Y0, 2);
                u64 X1p = shflx64(X1, 2), Y1p = shflx64(Y1, 2);
                u64 tX0 = fma2(Ax, X0, fma2(Bx, Y0, fma2(Cx, X0p, mul2(Dx, Y0p))));
                u64 tY0 = fma2(Ax, Y0, fma2(nBx, X0, fma2(Cx, Y0p, mul2(nDx, X0p))));
                u64 tX1 = fma2(Ax, X1, fma2(Bx, Y1, fma2(Cx, X1p, mul2(Dx, Y1p))));
                u64 tY1 = fma2(Ax, Y1, fma2(nBx, X1, fma2(Cx, Y1p, mul2(nDx, X1p))));
                X0 = tX0; Y0 = tY0; X1 = tX1; Y1 = tY1;
            }
            // ---- wire 1 (bit2, cross-lane xor 1) ----
            {
                u64 Ax = bc2(side1 ? -p1x : p1x);
                u64 Bx = bc2(-p1y);
                u64 Cx = bc2(q1x);
                u64 Dx = bc2(side1 ? q1y : -q1y);
                u64 nBx = neg2(Bx), nDx = neg2(Dx);
                u64 X0p = shflx64(X0, 1), Y0p = shflx64(Y0, 1);
                u64 X1p = shflx64(X1, 1), Y1p = shflx64(Y1, 1);
                u64 tX0 = fma2(Ax, X0, fma2(Bx, Y0, fma2(Cx, X0p, mul2(Dx, Y0p))));
                u64 tY0 = fma2(Ax, Y0, fma2(nBx, X0, fma2(Cx, Y0p, mul2(nDx, X0p))));
                u64 tX1 = fma2(Ax, X1, fma2(Bx, Y1, fma2(Cx, X1p, mul2(Dx, Y1p))));
                u64 tY1 = fma2(Ax, Y1, fma2(nBx, X1, fma2(Cx, Y1p, mul2(nDx, X1p))));
                X0 = tX0; Y0 = tY0; X1 = tX1; Y1 = tY1;
            }
            // ---- wire 2 (bit1, local: pairs across X0/X1) ----
            {
                u64 PX = bc2(p2x), PY = bc2(p2y), QX = bc2(q2x), QY = bc2(q2y);
                u64 PXn = neg2(PX), PYn = neg2(PY), QYn = neg2(QY);
                u64 tX0 = fma2(PX, X0, fma2(PYn, Y0, fma2(QX, X1, mul2(QYn, Y1))));
                u64 tY0 = fma2(PX, Y0, fma2(PY, X0, fma2(QX, Y1, mul2(QY, X1))));
                u64 tX1 = fma2(QX, X0, fma2(QY, Y0, fma2(PXn, X1, mul2(PYn, Y1))));
                u64 tY1 = fma2(QX, Y0, fma2(QYn, X0, fma2(PXn, Y1, mul2(PY, X1))));
                X0 = tX0; Y0 = tY0; X1 = tX1; Y1 = tY1;
            }
            // ---- wire 3 (bit0, intra-register coefficient form) ----
            {
                u64 A1 = pk2(p3x, q3x);
                u64 A2c = pk2(-p3y, q3y);
                u64 A3 = pk2(q3x, -p3x);
                u64 A4 = pk2(-q3y, -p3y);
                u64 B2c = pk2(p3y, -q3y);
                u64 B4c = pk2(q3y, p3y);
                {
                    float xa, xb, ya, yb;
                    unpk2(X0, xa, xb);
                    unpk2(Y0, ya, yb);
                    u64 bxa = bc2(xa), bxb = bc2(xb), bya = bc2(ya), byb = bc2(yb);
                    X0 = fma2(bxa, A1, fma2(bya, A2c, fma2(bxb, A3, mul2(byb, A4))));
                    Y0 = fma2(bya, A1, fma2(bxa, B2c, fma2(byb, A3, mul2(bxb, B4c))));
                }
                {
                    float xa, xb, ya, yb;
                    unpk2(X1, xa, xb);
                    unpk2(Y1, ya, yb);
                    u64 bxa = bc2(xa), bxb = bc2(xb), bya = bc2(ya), byb = bc2(yb);
                    X1 = fma2(bxa, A1, fma2(bya, A2c, fma2(bxb, A3, mul2(byb, A4))));
                    Y1 = fma2(bya, A1, fma2(bxa, B2c, fma2(byb, A3, mul2(bxb, B4c))));
                }
            }
            // ---- CRZ diagonal ----
            {
                u64 oX = X0, oY = Y0;
                X0 = fma2(PHX0, oX, neg2(mul2(PHY0, oY)));
                Y0 = fma2(PHX0, oY, mul2(PHY0, oX));
                oX = X1; oY = Y1;
                X1 = fma2(PHX1, oX, neg2(mul2(PHY1, oY)));
                Y1 = fma2(PHX1, oY, mul2(PHY1, oX));
            }

            // ---- measurement partials (rotated operator) ----
            u64 PR0 = fma2(Y0, Y0, mul2(X0, X0));
            u64 PR1 = fma2(Y1, Y1, mul2(X1, X1));
            float lo, hi;
            u64 tsum = add2(PR0, PR1);
            unpk2(tsum, lo, hi);
            float sum_pr = lo + hi;
            float d0p = sgn0 * sum_pr;
            float d1p = sgn1 * sum_pr;
            u64 tdif = sub2(PR0, PR1);
            unpk2(tdif, lo, hi);
            float d2p = lo + hi;
            unpk2(PR0, lo, hi);
            float d3p = lo - hi;
            unpk2(PR1, lo, hi);
            d3p += lo - hi;

            // local cross terms (wires 2,3)
            u64 xw2 = fma2(Y0, Y1, mul2(X0, X1));
            unpk2(xw2, lo, hi);
            float x2p = lo + hi;
            float x0a, x0b, y0a, y0b, x1a, x1b, y1a, y1b;
            unpk2(X0, x0a, x0b);
            unpk2(Y0, y0a, y0b);
            unpk2(X1, x1a, x1b);
            unpk2(Y1, y1a, y1b);
            float x3p = x0a * x0b + y0a * y0b + x1a * x1b + y1a * y1b;

            // cross-lane cross terms (wires 0,1) — double counted, use ms2h
            u64 X0q = shflx64(X0, 2), Y0q = shflx64(Y0, 2);
            u64 X1q = shflx64(X1, 2), Y1q = shflx64(Y1, 2);
            u64 cx = fma2(Y0, Y0q, mul2(X0, X0q));
            cx = fma2(Y1, Y1q, fma2(X1, X1q, cx));
            unpk2(cx, lo, hi);
            float x0p = lo + hi;
            X0q = shflx64(X0, 1); Y0q = shflx64(Y0, 1);
            X1q = shflx64(X1, 1); Y1q = shflx64(Y1, 1);
            cx = fma2(Y0, Y0q, mul2(X0, X0q));
            cx = fma2(Y1, Y1q, fma2(X1, X1q, cx));
            unpk2(cx, lo, hi);
            float x1p = lo + hi;

            float f0p = mc * d0p - ms2h * x0p;
            float f1p = mc * d1p - ms2h * x1p;
            float f2p = mc * d2p - ms2 * x2p;
            float f3p = mc * d3p - ms2 * x3p;

            // ---- reduce features across the quad ----
            u64 fA = pk2(f0p, f1p), fB = pk2(f2p, f3p);
            fA = add2(fA, shflx64(fA, 1));
            fA = add2(fA, shflx64(fA, 2));
            fB = add2(fB, shflx64(fB, 1));
            fB = add2(fB, shflx64(fB, 2));
            float f0, f1, f2, f3;
            unpk2(fA, f0, f1);
            unpk2(fB, f2, f3);

            // ---- fc1 accumulation: this lane handles rows r, r+4, ..., r+16
#pragma unroll
            for (int t = 0; t < 5; t++) {
                int jj = 4 * t + r;
                float4 wv = __ldg(&w4[jj * 196 + widx]);
                acc[t] += f0 * wv.x + f1 * wv.y + f2 * wv.z + f3 * wv.w;
            }

            Ab = a1;
            Bb = b1;
            widx++;
        }
    }

    // ---- fc1 bias + leaky relu + fc2 partials over owned rows ----
    float o0 = 0.f, o1 = 0.f;
#pragma unroll
    for (int t = 0; t < 5; t++) {
        int jj = 4 * t + r;
        float v = acc[t] + __ldg(fc1b + jj);
        v = v > 0.f ? v : 0.1f * v;
        o0 += v * __ldg(fc2w + jj);
        o1 += v * __ldg(fc2w + 20 + jj);
    }
    u64 po = pk2(o0, o1);
    po = add2(po, shflx64(po, 1));
    po = add2(po, shflx64(po, 2));
    if (r == 0 && img_raw < B) {
        float a, b;
        unpk2(po, a, b);
        reinterpret_cast<float2*>(out)[img] =
            make_float2(a + __ldg(fc2b + 0), b + __ldg(fc2b + 1));
    }
}

extern "C" void kernel_launch(void* const* d_in, const int* in_sizes, int n_in,
                              void* d_out, int out_size) {
    const float* x = (const float*)d_in[0];
    const float* crz_t = (const float*)d_in[1];
    const float* ry_t = (const float*)d_in[2];
    const float* fc1w = (const float*)d_in[3];
    const float* fc1b = (const float*)d_in[4];
    const float* fc2w = (const float*)d_in[5];
    const float* fc2b = (const float*)d_in[6];
    float* out = (float*)d_out;

    int B = in_sizes[0] / 784;
    int grid = (B + 31) / 32;   // 32 images per 128-thread block, 4 lanes/image
    multi_encoding_kernel<<<grid, 128>>>(x, crz_t, ry_t, fc1w, fc1b, fc2w,
                                         fc2b, out, B);
}